// round 11
// baseline (speedup 1.0000x reference)
#include <cuda_runtime.h>
#include <cuda_fp16.h>
#include <cuda_bf16.h>

// Problem constants
#define NB   32
#define RESO 256
#define KP   1024
#define FEPS 1e-6f
#define L2E  1.44269504088896340736f        // log2(e), T = 1
#define LN2F 0.69314718055994530942f

#define COLS_PER_BLK 32
#define IBLK         2                       // i-range halves per (n, tile)
#define I_PER_BLK    (KP / IBLK)             // 512 pairs per block
#define SPLITS       4                       // 128 thr = 32 cols x 4 splits
#define PAIRS_PER_T  (I_PER_BLK / SPLITS)    // 128 pairs per thread
#define Q_PER_T      (PAIRS_PER_T / 2)       // 64 float4 per thread
#define N_TILES      (NB * (KP / COLS_PER_BLK))   // 1024

// Scratch (allocation-free rule: __device__ globals). Stored PRE-SCALED by L2E.
__device__ __align__(16) float2 g_src_c[NB * KP];
__device__ __align__(16) float2 g_trg_c[NB * KP];
__device__ float  g_Scol[NB * KP];           // per-column sum of exp terms
__device__ unsigned int g_tile_cnt[N_TILES]; // arrivals of the IBLK i-halves
__device__ float  g_loss_acc;
__device__ float  g_vis_acc;
__device__ int    g_vis_mode;                // 0 = uint8, 1 = int32, 2 = float32
__device__ unsigned int g_fin_done;          // final-divide ticket (tiles)

__device__ __forceinline__ float fsqrt_ap(float x) {
    float r; asm("sqrt.approx.f32 %0, %1;" : "=f"(r) : "f"(x)); return r;
}
__device__ __forceinline__ float flg2_ap(float x) {
    float r; asm("lg2.approx.f32 %0, %1;" : "=f"(r) : "f"(x)); return r;
}
// pack two positive f32 distances, negate as f16x2, ONE MUFU ex2.f16x2.
__device__ __forceinline__ __half2 ex2n_pack(float a, float b) {
    unsigned int ru;
    asm("{\n\t.reg .b32 t;\n\t"
        "cvt.rn.f16x2.f32 t, %1, %2;\n\t"
        "neg.f16x2 t, t;\n\t"
        "ex2.approx.f16x2 %0, t;\n\t}"
        : "=r"(ru) : "f"(a), "f"(b));
    return *reinterpret_cast<__half2*>(&ru);
}
// +d (L2E-scaled): sqrt(dx^2 + dy^2)
__device__ __forceinline__ float pdist(float sx, float sy, float tnx, float tny) {
    float dx = sx + tnx;
    float dy = sy + tny;
    return fsqrt_ap(fmaf(dy, dy, dx * dx));
}

// Branch-free bilinear sample (keypoints are in [0, RES-1); min() is a guard).
// All 4 LDGs are unpredicated -> full MLP batching.
__device__ __forceinline__ float2 bilin(const float2* __restrict__ flow, float x, float y) {
    float x0f = floorf(x), y0f = floorf(y);
    int x0 = (int)x0f, y0 = (int)y0f;
    int x1 = min(x0 + 1, RESO - 1), y1 = min(y0 + 1, RESO - 1);
    x0 = min(x0, RESO - 1); y0 = min(y0, RESO - 1);
    float wx = x - x0f, wy = y - y0f;
    float2 v00 = __ldg(&flow[y0 * RESO + x0]);
    float2 v01 = __ldg(&flow[y0 * RESO + x1]);
    float2 v10 = __ldg(&flow[y1 * RESO + x0]);
    float2 v11 = __ldg(&flow[y1 * RESO + x1]);
    float w00 = (1.f - wx) * (1.f - wy), w01 = wx * (1.f - wy);
    float w10 = (1.f - wx) * wy,         w11 = wx * wy;
    float ax = fmaf(w00, v00.x, fmaf(w01, v01.x, fmaf(w10, v10.x, w11 * v11.x)));
    float ay = fmaf(w00, v00.y, fmaf(w01, v01.y, fmaf(w10, v10.y, w11 * v11.y)));
    return make_float2(ax, ay);
}

// ---------------------------------------------------------------------------
// Kernel 1 (fused): blocks 0..127 sample one keypoint (BOTH sides: 8 batched
// LDGs per thread for max MLP) + zero g_Scol/g_tile_cnt; block 128 detects
// kp_vis dtype and zeroes the scalar accumulators.
// ---------------------------------------------------------------------------
__global__ void __launch_bounds__(256)
sample_detect_kernel(const float* __restrict__ src_flow,
                     const float* __restrict__ trg_flow,
                     const float* __restrict__ src_kp,
                     const float* __restrict__ trg_kp,
                     const unsigned char* __restrict__ kp_vis) {
    if (blockIdx.x == 128) {
        // --- detection: nonzero-byte pattern per i%4 over first NB*KP bytes ---
        __shared__ int cnt[4];
        int tid = threadIdx.x;
        if (tid < 4) cnt[tid] = 0;
        __syncthreads();
        const uint4* v4 = (const uint4*)kp_vis;      // 32768 bytes = 2048 uint4
        int c0 = 0, c1 = 0, c2 = 0, c3 = 0;
#pragma unroll
        for (int k = 0; k < 8; k++) {
            uint4 w = v4[tid + k * 256];
            unsigned int ws[4] = {w.x, w.y, w.z, w.w};
#pragma unroll
            for (int q = 0; q < 4; q++) {
                c0 += (ws[q] & 0x000000FFu) != 0;
                c1 += (ws[q] & 0x0000FF00u) != 0;
                c2 += (ws[q] & 0x00FF0000u) != 0;
                c3 += (ws[q] & 0xFF000000u) != 0;
            }
        }
        atomicAdd(&cnt[0], c0); atomicAdd(&cnt[1], c1);
        atomicAdd(&cnt[2], c2); atomicAdd(&cnt[3], c3);
        __syncthreads();
        if (tid == 0) {
            int r0 = cnt[0], r1 = cnt[1], r2 = cnt[2], r3 = cnt[3];
            int mode;
            if (r0 > 0 && r1 == 0 && r2 == 0 && r3 == 0)       mode = 1; // int32
            else if (r0 == 0 && r1 == 0 && (r2 > 0 || r3 > 0)) mode = 2; // float32
            else                                               mode = 0; // uint8
            g_vis_mode = mode;
            g_loss_acc = 0.f;
            g_vis_acc  = 0.f;
            g_fin_done = 0u;
        }
        return;
    }
    int idx = blockIdx.x * blockDim.x + threadIdx.x;   // 0 .. 32767
    g_Scol[idx] = 0.f;
    if (idx < N_TILES) g_tile_cnt[idx] = 0u;
    int n = idx >> 10;
    const float2* sf = (const float2*)src_flow + (size_t)n * RESO * RESO;
    const float2* tf = (const float2*)trg_flow + (size_t)n * RESO * RESO;
    float2 sc = ((const float2*)src_kp)[idx];
    float2 tc = ((const float2*)trg_kp)[idx];
    float2 s = bilin(sf, sc.x, sc.y);
    float2 t = bilin(tf, tc.x, tc.y);
    g_src_c[idx] = make_float2(s.x * L2E, s.y * L2E);
    g_trg_c[idx] = make_float2(t.x * L2E, t.y * L2E);
}

// ---------------------------------------------------------------------------
// Kernel 2: partial logsumexp sums + fused CE epilogue + final divide.
// grid = (KP/32, NB, IBLK) = 2048 blocks x 128 thr (32 cols x 4 splits).
// Block (jt, n, ib) covers i in [ib*512, ib*512+512) for 32 columns; partial
// sums land in g_Scol via one atomicAdd per column. The SECOND arriving
// i-half block for a tile computes the CE for its 32 columns; the last tile
// overall performs the final divide.
// ---------------------------------------------------------------------------
__global__ void __launch_bounds__(128)
loss_kernel(const void* __restrict__ kp_vis,
            const float* __restrict__ kp_wt,
            float* __restrict__ out) {
    __shared__ float4 s_src4[I_PER_BLK / 2];   // 256 float4 = 4 KB
    __shared__ float  s_part[128];
    __shared__ unsigned int s_tk;

    int jt  = blockIdx.x;
    int n   = blockIdx.y;
    int ib  = blockIdx.z;
    int tid = threadIdx.x;

    const float4* src4 = (const float4*)(g_src_c + n * KP) + ib * (I_PER_BLK / 2);
    for (int i = tid; i < I_PER_BLK / 2; i += 128) s_src4[i] = src4[i];
    __syncthreads();

    int jl    = tid & (COLS_PER_BLK - 1);    // column within tile (0..31)
    int split = tid >> 5;                    // warp id (0..3)
    int j     = jt * COLS_PER_BLK + jl;      // global column

    float2 t  = g_trg_c[n * KP + j];
    float tnx = FEPS * L2E - t.x;            // d = s - t + eps (scaled units)
    float tny = FEPS * L2E - t.y;

    float S  = 0.f;
    int   q0 = split * Q_PER_T;              // 64 float4 per thread
    // 128 pairs = 8 flush groups x (4 k-steps x 4 pairs)
#pragma unroll 2
    for (int g = 0; g < Q_PER_T / 8; g++) {
        __half2 h0 = __float2half2_rn(0.f);
        __half2 h1 = __float2half2_rn(0.f);
#pragma unroll
        for (int k = 0; k < 4; k++) {
            int q = q0 + g * 8 + k * 2;
            float4 A = s_src4[q];
            float4 B = s_src4[q + 1];
            float dA0 = pdist(A.x, A.y, tnx, tny);
            float dA1 = pdist(A.z, A.w, tnx, tny);
            float dB0 = pdist(B.x, B.y, tnx, tny);
            float dB1 = pdist(B.z, B.w, tnx, tny);
            h0 = __hadd2(h0, ex2n_pack(dA0, dA1));
            h1 = __hadd2(h1, ex2n_pack(dB0, dB1));
        }
        float2 f0 = __half22float2(h0);      // half-sums <= 4: low error
        float2 f1 = __half22float2(h1);
        S += (f0.x + f0.y) + (f1.x + f1.y);
    }
    s_part[tid] = S;
    __syncthreads();

    // warp 0 accumulates this block's partials into g_Scol, then the second
    // arriving i-half block for the tile runs the CE epilogue.
    if (split == 0) {
        float Sp = s_part[jl] + s_part[jl + 32] + s_part[jl + 64] + s_part[jl + 96];
        atomicAdd(&g_Scol[n * KP + j], Sp);
        __threadfence();
        __syncwarp();
        if (jl == 0)
            s_tk = atomicAdd(&g_tile_cnt[n * (KP / COLS_PER_BLK) + jt], 1u);
        __syncwarp();
        if (s_tk == IBLK - 1) {
            // all IBLK partial adds are globally visible (fence -> ticket)
            int idx = n * KP + j;
            float Stot = __ldcg(&g_Scol[idx]);
            float2 sj  = g_src_c[idx];
            float djj  = pdist(sj.x, sj.y, tnx, tny);       // exact diag (f32)
            float ce   = LN2F * (flg2_ap(Stot) + djj);
            int mode = g_vis_mode;
            float vv;
            if (mode == 0)      vv = ((const unsigned char*)kp_vis)[idx] ? 1.f : 0.f;
            else if (mode == 1) vv = ((const int*)kp_vis)[idx] ? 1.f : 0.f;
            else                vv = (((const float*)kp_vis)[idx] != 0.f) ? 1.f : 0.f;
            float contrib = 2.f * ce * vv * kp_wt[idx];
#pragma unroll
            for (int off = 16; off; off >>= 1) {
                contrib += __shfl_down_sync(0xffffffff, contrib, off);
                vv      += __shfl_down_sync(0xffffffff, vv, off);
            }
            if (jl == 0) {
                atomicAdd(&g_loss_acc, contrib);
                atomicAdd(&g_vis_acc, vv);
                __threadfence();
                unsigned int fk = atomicAdd(&g_fin_done, 1u);
                if (fk == N_TILES - 1) {
                    float num = atomicAdd(&g_loss_acc, 0.f);
                    float den = atomicAdd(&g_vis_acc, 0.f);
                    out[0] = num / den;
                }
            }
        }
    }
}

extern "C" void kernel_launch(void* const* d_in, const int* in_sizes, int n_in,
                              void* d_out, int out_size) {
    const float* src_flow = (const float*)d_in[0];
    const float* trg_flow = (const float*)d_in[1];
    const float* src_kp   = (const float*)d_in[2];
    const float* trg_kp   = (const float*)d_in[3];
    const void*  kp_vis   = d_in[4];
    const float* kp_wt    = (const float*)d_in[5];
    float* out = (float*)d_out;

    sample_detect_kernel<<<129, 256>>>(src_flow, trg_flow, src_kp, trg_kp,
                                       (const unsigned char*)kp_vis);
    dim3 grid(KP / COLS_PER_BLK, NB, IBLK);
    loss_kernel<<<grid, 128>>>(kp_vis, kp_wt, out);
}

// round 12
// speedup vs baseline: 1.2073x; 1.2073x over previous
#include <cuda_runtime.h>
#include <cuda_fp16.h>
#include <cuda_bf16.h>

// Problem constants
#define NB   32
#define RESO 256
#define KP   1024
#define FEPS 1e-6f
#define L2E  1.44269504088896340736f        // log2(e), T = 1
#define LN2F 0.69314718055994530942f

#define COLS_PER_BLK 32
#define SPLITS       8                       // 256 threads = 32 cols x 8 splits
#define ITERS        (KP / SPLITS)           // 128 pairs per thread
#define LOSS_BLOCKS  (NB * (KP / COLS_PER_BLK))   // 1024

// Scratch (allocation-free rule: __device__ globals). Stored PRE-SCALED by L2E.
__device__ __align__(16) float2 g_src_c[NB * KP];
__device__ __align__(16) float2 g_trg_c[NB * KP];
__device__ float  g_loss_acc;
__device__ float  g_vis_acc;
__device__ int    g_vis_mode;                // 0 = uint8, 1 = int32, 2 = float32
__device__ unsigned int g_done;

__device__ __forceinline__ float fsqrt_ap(float x) {
    float r; asm("sqrt.approx.f32 %0, %1;" : "=f"(r) : "f"(x)); return r;
}
__device__ __forceinline__ float flg2_ap(float x) {
    float r; asm("lg2.approx.f32 %0, %1;" : "=f"(r) : "f"(x)); return r;
}

// Two pairs' exp(-dist) in one f16x2, using packed f32x2 arithmetic:
//   dd = s + tn (both lanes), qq = dd*dd, d2 = lane0+lane1, sqrt, pack,
//   negate, ONE MUFU ex2.f16x2.
__device__ __forceinline__ unsigned int two_exp(unsigned long long sp0,
                                                unsigned long long sp1,
                                                unsigned long long tn) {
    unsigned int e;
    asm("{\n\t"
        ".reg .b64 dd0, dd1, qq0, qq1;\n\t"
        ".reg .f32 a0, b0, a1, b1, d0, d1, r0, r1;\n\t"
        ".reg .b32 t;\n\t"
        "add.rn.f32x2 dd0, %1, %3;\n\t"
        "add.rn.f32x2 dd1, %2, %3;\n\t"
        "mul.rn.f32x2 qq0, dd0, dd0;\n\t"
        "mul.rn.f32x2 qq1, dd1, dd1;\n\t"
        "mov.b64 {a0, b0}, qq0;\n\t"
        "mov.b64 {a1, b1}, qq1;\n\t"
        "add.f32 d0, a0, b0;\n\t"
        "add.f32 d1, a1, b1;\n\t"
        "sqrt.approx.f32 r0, d0;\n\t"
        "sqrt.approx.f32 r1, d1;\n\t"
        "cvt.rn.f16x2.f32 t, r0, r1;\n\t"
        "neg.f16x2 t, t;\n\t"
        "ex2.approx.f16x2 %0, t;\n\t"
        "}" : "=r"(e) : "l"(sp0), "l"(sp1), "l"(tn));
    return e;
}
// scalar +d (L2E-scaled) for the diagonal
__device__ __forceinline__ float pdist(float sx, float sy, float tnx, float tny) {
    float dx = sx + tnx;
    float dy = sy + tny;
    return fsqrt_ap(fmaf(dy, dy, dx * dx));
}

// Branch-free bilinear sample (keypoints in [0, RES-1); min() is a guard).
__device__ __forceinline__ float2 bilin(const float2* __restrict__ flow, float x, float y) {
    float x0f = floorf(x), y0f = floorf(y);
    int x0 = (int)x0f, y0 = (int)y0f;
    int x1 = min(x0 + 1, RESO - 1), y1 = min(y0 + 1, RESO - 1);
    x0 = min(x0, RESO - 1); y0 = min(y0, RESO - 1);
    float wx = x - x0f, wy = y - y0f;
    float2 v00 = __ldg(&flow[y0 * RESO + x0]);
    float2 v01 = __ldg(&flow[y0 * RESO + x1]);
    float2 v10 = __ldg(&flow[y1 * RESO + x0]);
    float2 v11 = __ldg(&flow[y1 * RESO + x1]);
    float w00 = (1.f - wx) * (1.f - wy), w01 = wx * (1.f - wy);
    float w10 = (1.f - wx) * wy,         w11 = wx * wy;
    float ax = fmaf(w00, v00.x, fmaf(w01, v01.x, fmaf(w10, v10.x, w11 * v11.x)));
    float ay = fmaf(w00, v00.y, fmaf(w01, v01.y, fmaf(w10, v10.y, w11 * v11.y)));
    return make_float2(ax, ay);
}

// ---------------------------------------------------------------------------
// Kernel 1 (fused): blocks 0..127 sample one keypoint per thread (both sides,
// 8 batched LDGs); block 128 detects kp_vis dtype + zeroes accumulators.
// ---------------------------------------------------------------------------
__global__ void __launch_bounds__(256)
sample_detect_kernel(const float* __restrict__ src_flow,
                     const float* __restrict__ trg_flow,
                     const float* __restrict__ src_kp,
                     const float* __restrict__ trg_kp,
                     const unsigned char* __restrict__ kp_vis) {
    if (blockIdx.x == 128) {
        // --- detection: nonzero-byte pattern per i%4 over first NB*KP bytes ---
        __shared__ int cnt[4];
        int tid = threadIdx.x;
        if (tid < 4) cnt[tid] = 0;
        __syncthreads();
        const uint4* v4 = (const uint4*)kp_vis;      // 32768 bytes = 2048 uint4
        int c0 = 0, c1 = 0, c2 = 0, c3 = 0;
#pragma unroll
        for (int k = 0; k < 8; k++) {
            uint4 w = v4[tid + k * 256];
            unsigned int ws[4] = {w.x, w.y, w.z, w.w};
#pragma unroll
            for (int q = 0; q < 4; q++) {
                c0 += (ws[q] & 0x000000FFu) != 0;
                c1 += (ws[q] & 0x0000FF00u) != 0;
                c2 += (ws[q] & 0x00FF0000u) != 0;
                c3 += (ws[q] & 0xFF000000u) != 0;
            }
        }
        atomicAdd(&cnt[0], c0); atomicAdd(&cnt[1], c1);
        atomicAdd(&cnt[2], c2); atomicAdd(&cnt[3], c3);
        __syncthreads();
        if (tid == 0) {
            int r0 = cnt[0], r1 = cnt[1], r2 = cnt[2], r3 = cnt[3];
            int mode;
            if (r0 > 0 && r1 == 0 && r2 == 0 && r3 == 0)       mode = 1; // int32
            else if (r0 == 0 && r1 == 0 && (r2 > 0 || r3 > 0)) mode = 2; // float32
            else                                               mode = 0; // uint8
            g_vis_mode = mode;
            g_loss_acc = 0.f;
            g_vis_acc  = 0.f;
            g_done     = 0u;
        }
        return;
    }
    int idx = blockIdx.x * blockDim.x + threadIdx.x;   // 0 .. 32767
    int n = idx >> 10;
    const float2* sf = (const float2*)src_flow + (size_t)n * RESO * RESO;
    const float2* tf = (const float2*)trg_flow + (size_t)n * RESO * RESO;
    float2 sc = ((const float2*)src_kp)[idx];
    float2 tc = ((const float2*)trg_kp)[idx];
    float2 s = bilin(sf, sc.x, sc.y);
    float2 t = bilin(tf, tc.x, tc.y);
    g_src_c[idx] = make_float2(s.x * L2E, s.y * L2E);
    g_trg_c[idx] = make_float2(t.x * L2E, t.y * L2E);
}

// ---------------------------------------------------------------------------
// Kernel 2: per-column logsumexp + CE in base-2 units, fused finalize.
// grid = (KP/32, NB) = 1024 blocks; block = 256 = 32 columns x 8 i-splits.
// Inner loop: ld.shared.v2.u64 delivers packed (x,y) pairs; add/mul.f32x2
// halve the fma-pipe ops; one MUFU ex2.f16x2 per 2 pairs; dual half2 chains.
// ---------------------------------------------------------------------------
__global__ void __launch_bounds__(256)
loss_kernel(const void* __restrict__ kp_vis,
            const float* __restrict__ kp_wt,
            float* __restrict__ out) {
    __shared__ __align__(16) float2 s_src[KP];   // 8 KB (scaled by L2E)
    __shared__ float s_part[256];                // 1 KB

    int n   = blockIdx.y;
    int jt  = blockIdx.x;
    int tid = threadIdx.x;

    const float4* src4 = (const float4*)(g_src_c + n * KP);
    float4* dst4 = (float4*)s_src;
    for (int i = tid; i < KP / 2; i += 256) dst4[i] = src4[i];
    __syncthreads();

    int jl    = tid & (COLS_PER_BLK - 1);    // column within tile
    int split = tid >> 5;                    // 0..7 (warp id)
    int j     = jt * COLS_PER_BLK + jl;      // global column

    float2 t  = g_trg_c[n * KP + j];
    float tnx = FEPS * L2E - t.x;            // d = s - t + eps (scaled units)
    float tny = FEPS * L2E - t.y;
    unsigned long long tn;
    asm("mov.b64 %0, {%1, %2};" : "=l"(tn) : "f"(tnx), "f"(tny));

    // shared address of this thread's first pair (16B per 2 pairs)
    unsigned int sbase = (unsigned int)__cvta_generic_to_shared(s_src)
                       + (unsigned int)(split * ITERS) * 8u;

    float S = 0.f;
    // 128 pairs = 8 flush groups x (4 k-steps x 4 pairs)
#pragma unroll 2
    for (int g = 0; g < ITERS / 16; g++) {
        __half2 h0 = __float2half2_rn(0.f);
        __half2 h1 = __float2half2_rn(0.f);
#pragma unroll
        for (int k = 0; k < 4; k++) {
            unsigned int addr = sbase + (unsigned)(g * 128 + k * 32);
            unsigned long long sp0, sp1, sp2, sp3;
            asm("ld.shared.v2.u64 {%0, %1}, [%2];"
                : "=l"(sp0), "=l"(sp1) : "r"(addr));
            asm("ld.shared.v2.u64 {%0, %1}, [%2+16];"
                : "=l"(sp2), "=l"(sp3) : "r"(addr));
            unsigned int e0 = two_exp(sp0, sp1, tn);
            unsigned int e1 = two_exp(sp2, sp3, tn);
            h0 = __hadd2(h0, *reinterpret_cast<__half2*>(&e0));
            h1 = __hadd2(h1, *reinterpret_cast<__half2*>(&e1));
        }
        float2 f0 = __half22float2(h0);      // half-sums <= 4: low error
        float2 f1 = __half22float2(h1);
        S += (f0.x + f0.y) + (f1.x + f1.y);
    }
    s_part[tid] = S;
    __syncthreads();

    // warp 0 (split==0) owns the 32 columns of this tile
    if (split == 0) {
        float Stot = 0.f;
#pragma unroll
        for (int k = 0; k < SPLITS; k++) Stot += s_part[jl + k * COLS_PER_BLK];
        float2 sj  = s_src[j];
        float djj  = pdist(sj.x, sj.y, tnx, tny);           // exact diag (f32)
        // ce = ln(S) + dist = LN2 * (lg2(S) + d'jj); d1==d2 forward -> x2
        float ce = LN2F * (flg2_ap(Stot) + djj);
        int idx = n * KP + j;
        int mode = g_vis_mode;
        float vv;
        if (mode == 0)      vv = ((const unsigned char*)kp_vis)[idx] ? 1.f : 0.f;
        else if (mode == 1) vv = ((const int*)kp_vis)[idx] ? 1.f : 0.f;
        else                vv = (((const float*)kp_vis)[idx] != 0.f) ? 1.f : 0.f;
        float contrib = 2.f * ce * vv * kp_wt[idx];

#pragma unroll
        for (int off = 16; off; off >>= 1) {
            contrib += __shfl_down_sync(0xffffffff, contrib, off);
            vv      += __shfl_down_sync(0xffffffff, vv, off);
        }
        if (jl == 0) {
            atomicAdd(&g_loss_acc, contrib);
            atomicAdd(&g_vis_acc, vv);
            __threadfence();
            unsigned int ticket = atomicAdd(&g_done, 1u);
            if (ticket == LOSS_BLOCKS - 1) {
                float num = atomicAdd(&g_loss_acc, 0.f);
                float den = atomicAdd(&g_vis_acc, 0.f);
                out[0] = num / den;
            }
        }
    }
}

extern "C" void kernel_launch(void* const* d_in, const int* in_sizes, int n_in,
                              void* d_out, int out_size) {
    const float* src_flow = (const float*)d_in[0];
    const float* trg_flow = (const float*)d_in[1];
    const float* src_kp   = (const float*)d_in[2];
    const float* trg_kp   = (const float*)d_in[3];
    const void*  kp_vis   = d_in[4];
    const float* kp_wt    = (const float*)d_in[5];
    float* out = (float*)d_out;

    sample_detect_kernel<<<129, 256>>>(src_flow, trg_flow, src_kp, trg_kp,
                                       (const unsigned char*)kp_vis);
    dim3 grid(KP / COLS_PER_BLK, NB);
    loss_kernel<<<grid, 256>>>(kp_vis, kp_wt, out);
}